// round 12
// baseline (speedup 1.0000x reference)
#include <cuda_runtime.h>
#include <cstdint>

// Problem constants.
#define NTOK 16384
#define DIN  2048
#define DOUT 2048
#define NEXP 8

// GEMM tiling: 128x256 CTA tile, 16 warps (32x64 each, 4x4 grid).
#define BM 128
#define BN 256
#define BK 32                      // floats per K stage = 128 bytes per row
#define NSTG (DIN / BK)            // 64 stages
#define ST 4                       // cp.async ring depth
#define MAXT (NTOK / BM + NEXP)    // 136 m-tiles worst case
#define PADN (MAXT * BM)           // 17408

// SMEM layout (dynamic, offsets from 1024-aligned base).
#define SM_TOK   0                 // 128 ints
#define SM_STG0  1024
#define STGB     49152             // 48 KB per stage: A(16K) + B(32K)
#define BOFF     16384
#define SMEM_REQ (SM_STG0 + ST * STGB + 1024)

#define SW128(o) ((o) ^ (((o) >> 3) & 0x70))

// Scratch (device globals are the sanctioned scratch; no allocations allowed).
__device__ int g_sorted[PADN];
__device__ int g_tile_expert[MAXT];
__device__ __align__(16) float g_Wr[NEXP * DOUT * DIN];   // rna-rounded W
__device__ __align__(16) float g_Xs[PADN * DIN];          // gathered+rounded x

// ---------------------------------------------------------------------------
// PTX helpers (baseline PTX only — no 'a'-suffix features).
// ---------------------------------------------------------------------------
__device__ __forceinline__ void cp16(uint32_t dst, const void* src) {
    asm volatile("cp.async.cg.shared.global [%0], [%1], 16;"
                 :: "r"(dst), "l"(src));
}
__device__ __forceinline__ void cp_commit() {
    asm volatile("cp.async.commit_group;" ::: "memory");
}
__device__ __forceinline__ void cp_wait2() {
    asm volatile("cp.async.wait_group 2;" ::: "memory");
}
__device__ __forceinline__ void ldsm4(uint32_t& r0, uint32_t& r1, uint32_t& r2,
                                      uint32_t& r3, uint32_t addr) {
    asm volatile("ldmatrix.sync.aligned.m8n8.x4.shared.b16 {%0,%1,%2,%3}, [%4];"
                 : "=r"(r0), "=r"(r1), "=r"(r2), "=r"(r3) : "r"(addr));
}
// Round-to-nearest fp32 -> tf32 bits (done once in k_prep, not in GEMM loop).
__device__ __forceinline__ uint32_t rna(uint32_t v) {
    uint32_t r;
    asm("cvt.rna.tf32.f32 %0, %1;" : "=r"(r) : "r"(v));
    return r;
}
__device__ __forceinline__ void mma_tf32(float* d, const uint32_t* a,
                                         const uint32_t* b) {
    asm volatile(
        "mma.sync.aligned.m16n8k8.row.col.f32.tf32.tf32.f32 "
        "{%0,%1,%2,%3}, {%4,%5,%6,%7}, {%8,%9}, {%0,%1,%2,%3};"
        : "+f"(d[0]), "+f"(d[1]), "+f"(d[2]), "+f"(d[3])
        : "r"(a[0]), "r"(a[1]), "r"(a[2]), "r"(a[3]), "r"(b[0]), "r"(b[1]));
}

// ---------------------------------------------------------------------------
// Fused routing: ONE CTA.
// ---------------------------------------------------------------------------
__global__ void k_route(const void* __restrict__ idxs) {
    __shared__ int h[NEXP], fill_s[NEXP];
    __shared__ int s_is64;
    const int tid = threadIdx.x;

    if (tid == 0) {
        const int* p = (const int*)idxs;
        int is64 = 1;
        for (int t = 0; t < 32; t++)
            if (p[2 * t + 1] != 0) { is64 = 0; break; }
        s_is64 = is64;
    }
    if (tid < NEXP) h[tid] = 0;
    for (int i = tid; i < PADN; i += 1024) g_sorted[i] = -1;
    __syncthreads();

    const int is64 = s_is64;
    const long long* p64 = (const long long*)idxs;
    const int* p32 = (const int*)idxs;

    for (int i = tid; i < NTOK; i += 1024)
        atomicAdd(&h[is64 ? (int)p64[i] : p32[i]], 1);
    __syncthreads();

    if (tid == 0) {
        int off = 0;
        for (int e = 0; e < NEXP; e++) {
            fill_s[e] = off;
            int nt = (h[e] + BM - 1) / BM;
            for (int t = 0; t < nt; t++) g_tile_expert[off / BM + t] = e;
            off += nt * BM;
        }
        for (int t = off / BM; t < MAXT; t++) g_tile_expert[t] = -1;
    }
    __syncthreads();

    for (int i = tid; i < NTOK; i += 1024) {
        int e = is64 ? (int)p64[i] : p32[i];
        int pos = atomicAdd(&fill_s[e], 1);
        g_sorted[pos] = i;
    }
}

// ---------------------------------------------------------------------------
// Preprocess: round W -> g_Wr; gather + round x into sorted order -> g_Xs.
// ---------------------------------------------------------------------------
__global__ void k_prep(const float* __restrict__ x, const float* __restrict__ W) {
    const int gt = blockIdx.x * blockDim.x + threadIdx.x;
    const int gs = gridDim.x * blockDim.x;

    const uint4* W4 = (const uint4*)W;
    uint4* Wr4 = (uint4*)g_Wr;
    for (int i = gt; i < NEXP * DOUT * DIN / 4; i += gs) {
        uint4 v = W4[i];
        v.x = rna(v.x); v.y = rna(v.y); v.z = rna(v.z); v.w = rna(v.w);
        Wr4[i] = v;
    }

    const uint4* x4 = (const uint4*)x;
    uint4* Xs4 = (uint4*)g_Xs;
    for (int i = gt; i < PADN * DIN / 4; i += gs) {
        const int slot = i >> 9;               // DIN/4 = 512 float4 per row
        const int k4 = i & 511;
        const int tok = g_sorted[slot];
        uint4 v = {0u, 0u, 0u, 0u};
        if (tok >= 0) {
            v = x4[(size_t)tok * 512 + k4];
            v.x = rna(v.x); v.y = rna(v.y); v.z = rna(v.z); v.w = rna(v.w);
        }
        Xs4[i] = v;
    }
}

// ---------------------------------------------------------------------------
// tf32 mma.sync grouped GEMM: 128x256 CTA, 16 warps (32x64 each), BK=32,
// ST=4 cp.async ring (prefetch distance 2), one sync per stage, SW128
// ldmatrix, cvt-free inner loop, ks-level register fragment double-buffer.
//   y[tok] = relu(x[tok] @ W[e]^T + b[e]).
// ---------------------------------------------------------------------------
__global__ void __launch_bounds__(512, 1)
k_gemm_mma(const float* __restrict__ bias, float* __restrict__ out) {
    extern __shared__ char smem_raw[];
    const int mt_blk = blockIdx.y;
    const int e = g_tile_expert[mt_blk];
    if (e < 0) return;
    const int n0 = blockIdx.x * BN;
    const int tid = threadIdx.x;
    const int wid = tid >> 5;
    const int lane = tid & 31;

    uint32_t sraw = (uint32_t)__cvta_generic_to_shared(smem_raw);
    uint32_t sbase = (sraw + 1023) & ~1023u;
    char* smem = smem_raw + (sbase - sraw);
    int* s_tok = (int*)(smem + SM_TOK);

    if (tid < BM) s_tok[tid] = g_sorted[mt_blk * BM + tid];
    __syncthreads();

    // ---- Producer geometry (512 threads):
    // A: 4 threads per row, 2x16B chunks each.  B: 2 threads per row, 4x16B.
    const int arow = tid >> 2;
    const int acb = (tid & 3) * 2;
    const float* asrc = g_Xs + (size_t)mt_blk * BM * DIN + (size_t)arow * DIN;
    const int brow = tid >> 1;
    const int bcb = (tid & 1) * 4;
    const float* bsrc = g_Wr + (size_t)e * DOUT * DIN + (size_t)(n0 + brow) * DIN;

    uint32_t aoff[2], boff[4];
#pragma unroll
    for (int j = 0; j < 2; j++)
        aoff[j] = SW128((uint32_t)(arow * 128 + (acb + j) * 16));
#pragma unroll
    for (int j = 0; j < 4; j++)
        boff[j] = SW128((uint32_t)(brow * 128 + (bcb + j) * 16));

    auto issue = [&](int it, int bf) {
        const int k0 = it * BK;
        const uint32_t stg = sbase + SM_STG0 + bf * STGB;
#pragma unroll
        for (int j = 0; j < 2; j++)
            cp16(stg + aoff[j], asrc + k0 + (acb + j) * 4);
#pragma unroll
        for (int j = 0; j < 4; j++)
            cp16(stg + BOFF + boff[j], bsrc + k0 + (bcb + j) * 4);
    };

    // ---- ldmatrix lane addressing (32x64 warp tiles, 4x4 warp grid).
    const int g = lane >> 3;
    const int gr = lane & 7;
    const int wm = (wid >> 2) * 32;
    const int wn = (wid & 3) * 64;
    const int a_row_off = wm + ((g & 1) << 3) + gr;
    const int a_kbyte = (g >> 1) << 4;
    const int b_row_off = wn + ((g >> 1) << 3) + gr;
    const int b_kbyte = (g & 1) << 4;

    float acc[2][8][4];
#pragma unroll
    for (int i = 0; i < 2; i++)
#pragma unroll
        for (int j = 0; j < 8; j++)
#pragma unroll
            for (int q = 0; q < 4; q++) acc[i][j][q] = 0.f;

    issue(0, 0); cp_commit();
    issue(1, 1); cp_commit();
    issue(2, 2); cp_commit();

    for (int it = 0; it < NSTG; ++it) {
        const int st = it & (ST - 1);
        cp_wait2();                          // group 'it' complete, 2 in flight
        __syncthreads();
        if (it + 3 < NSTG) issue(it + 3, (it + 3) & (ST - 1));
        cp_commit();                         // empty commits at tail keep count

        const uint32_t aS = sbase + SM_STG0 + st * STGB;
        const uint32_t bS = aS + BOFF;

        // Register fragment double-buffer over the 4 ks steps.
        uint32_t aF[2][2][4], bF[2][8][2];
        auto ldfr = [&](int ks, int buf) {
#pragma unroll
            for (int mt = 0; mt < 2; mt++) {
                uint32_t addr = aS + SW128((uint32_t)((a_row_off + mt * 16) * 128
                                                      + ks * 32 + a_kbyte));
                ldsm4(aF[buf][mt][0], aF[buf][mt][1],
                      aF[buf][mt][2], aF[buf][mt][3], addr);
            }
#pragma unroll
            for (int ntp = 0; ntp < 4; ntp++) {
                uint32_t addr = bS + SW128((uint32_t)((b_row_off + ntp * 16) * 128
                                                      + ks * 32 + b_kbyte));
                ldsm4(bF[buf][2 * ntp][0], bF[buf][2 * ntp][1],
                      bF[buf][2 * ntp + 1][0], bF[buf][2 * ntp + 1][1], addr);
            }
        };

        ldfr(0, 0);
#pragma unroll
        for (int ks = 0; ks < 4; ks++) {
            const int cur = ks & 1;
            if (ks < 3) ldfr(ks + 1, cur ^ 1);   // prefetch under MMA chain
#pragma unroll
            for (int mt = 0; mt < 2; mt++)
#pragma unroll
                for (int nt = 0; nt < 8; nt++)
                    mma_tf32(acc[mt][nt], aF[cur][mt], bF[cur][nt]);
        }
    }

    // ---- Epilogue: bias + ReLU, scatter to token rows.
    const int erow = wm + (lane >> 2);
    const int ecol = n0 + wn + ((lane & 3) << 1);
    float2 bv[8];
#pragma unroll
    for (int nt = 0; nt < 8; nt++)
        bv[nt] = *(const float2*)&bias[(size_t)e * DOUT + ecol + nt * 8];

#pragma unroll
    for (int mt = 0; mt < 2; mt++) {
#pragma unroll
        for (int v = 0; v < 2; v++) {
            const int row = erow + mt * 16 + v * 8;
            const int tok = s_tok[row];
            if (tok < 0) continue;
            float* o = out + (size_t)tok * DOUT + ecol;
#pragma unroll
            for (int nt = 0; nt < 8; nt++) {
                float2 r;
                r.x = fmaxf(acc[mt][nt][2 * v + 0] + bv[nt].x, 0.f);
                r.y = fmaxf(acc[mt][nt][2 * v + 1] + bv[nt].y, 0.f);
                *(float2*)(o + nt * 8) = r;
            }
        }
    }
}

// ---------------------------------------------------------------------------
// Launch: 3 kernels per call (route, prep, gemm).
// ---------------------------------------------------------------------------
extern "C" void kernel_launch(void* const* d_in, const int* in_sizes, int n_in,
                              void* d_out, int out_size) {
    const float* x    = (const float*)d_in[0];
    const void*  idxs = d_in[1];
    const float* W    = (const float*)d_in[2];
    const float* b    = (const float*)d_in[3];
    float* out = (float*)d_out;

    k_route<<<1, 1024>>>(idxs);
    k_prep<<<2048, 256>>>(x, W);

    cudaFuncSetAttribute(k_gemm_mma, cudaFuncAttributeMaxDynamicSharedMemorySize,
                         SMEM_REQ);
    dim3 grid(DOUT / BN, MAXT);            // (8, 136)
    k_gemm_mma<<<grid, 512, SMEM_REQ>>>(b, out);
}

// round 13
// speedup vs baseline: 1.0441x; 1.0441x over previous
#include <cuda_runtime.h>
#include <cstdint>

// Problem constants.
#define NTOK 16384
#define DIN  2048
#define DOUT 2048
#define NEXP 8

// GEMM tiling: 128x256 CTA tile, 16 warps (32x64 each, 4x4 grid).
#define BM 128
#define BN 256
#define BK 32                      // floats per K stage = 128 bytes per row
#define NSTG (DIN / BK)            // 64 stages
#define ST 4                       // cp.async ring depth
#define MAXT (NTOK / BM + NEXP)    // 136 m-tiles worst case
#define PADN (MAXT * BM)           // 17408

// SMEM layout (dynamic, offsets from 1024-aligned base).
#define SM_TOK   0                 // 128 ints
#define SM_STG0  1024
#define STGB     49152             // 48 KB per stage: A(16K) + B(32K)
#define BOFF     16384
#define SMEM_REQ (SM_STG0 + ST * STGB + 1024)

#define SW128(o) ((o) ^ (((o) >> 3) & 0x70))

// Scratch (device globals are the sanctioned scratch; no allocations allowed).
__device__ int g_sorted[PADN];
__device__ int g_tile_expert[MAXT];
__device__ __align__(16) float g_Xs[PADN * DIN];          // gathered+rounded x

// ---------------------------------------------------------------------------
// PTX helpers (baseline PTX only — no 'a'-suffix features).
// ---------------------------------------------------------------------------
__device__ __forceinline__ void cp16(uint32_t dst, const void* src) {
    asm volatile("cp.async.cg.shared.global [%0], [%1], 16;"
                 :: "r"(dst), "l"(src));
}
__device__ __forceinline__ void cp_commit() {
    asm volatile("cp.async.commit_group;" ::: "memory");
}
__device__ __forceinline__ void cp_wait2() {
    asm volatile("cp.async.wait_group 2;" ::: "memory");
}
__device__ __forceinline__ void ldsm4(uint32_t& r0, uint32_t& r1, uint32_t& r2,
                                      uint32_t& r3, uint32_t addr) {
    asm volatile("ldmatrix.sync.aligned.m8n8.x4.shared.b16 {%0,%1,%2,%3}, [%4];"
                 : "=r"(r0), "=r"(r1), "=r"(r2), "=r"(r3) : "r"(addr));
}
// Round-to-nearest fp32 -> tf32 bits (applied to x only, in k_prep).
__device__ __forceinline__ uint32_t rna(uint32_t v) {
    uint32_t r;
    asm("cvt.rna.tf32.f32 %0, %1;" : "=r"(r) : "r"(v));
    return r;
}
__device__ __forceinline__ void mma_tf32(float* d, const uint32_t* a,
                                         const uint32_t* b) {
    asm volatile(
        "mma.sync.aligned.m16n8k8.row.col.f32.tf32.tf32.f32 "
        "{%0,%1,%2,%3}, {%4,%5,%6,%7}, {%8,%9}, {%0,%1,%2,%3};"
        : "+f"(d[0]), "+f"(d[1]), "+f"(d[2]), "+f"(d[3])
        : "r"(a[0]), "r"(a[1]), "r"(a[2]), "r"(a[3]), "r"(b[0]), "r"(b[1]));
}

// ---------------------------------------------------------------------------
// Fused routing: ONE CTA.
// ---------------------------------------------------------------------------
__global__ void k_route(const void* __restrict__ idxs) {
    __shared__ int h[NEXP], fill_s[NEXP];
    __shared__ int s_is64;
    const int tid = threadIdx.x;

    if (tid == 0) {
        const int* p = (const int*)idxs;
        int is64 = 1;
        for (int t = 0; t < 32; t++)
            if (p[2 * t + 1] != 0) { is64 = 0; break; }
        s_is64 = is64;
    }
    if (tid < NEXP) h[tid] = 0;
    for (int i = tid; i < PADN; i += 1024) g_sorted[i] = -1;
    __syncthreads();

    const int is64 = s_is64;
    const long long* p64 = (const long long*)idxs;
    const int* p32 = (const int*)idxs;

    for (int i = tid; i < NTOK; i += 1024)
        atomicAdd(&h[is64 ? (int)p64[i] : p32[i]], 1);
    __syncthreads();

    if (tid == 0) {
        int off = 0;
        for (int e = 0; e < NEXP; e++) {
            fill_s[e] = off;
            int nt = (h[e] + BM - 1) / BM;
            for (int t = 0; t < nt; t++) g_tile_expert[off / BM + t] = e;
            off += nt * BM;
        }
        for (int t = off / BM; t < MAXT; t++) g_tile_expert[t] = -1;
    }
    __syncthreads();

    for (int i = tid; i < NTOK; i += 1024) {
        int e = is64 ? (int)p64[i] : p32[i];
        int pos = atomicAdd(&fill_s[e], 1);
        g_sorted[pos] = i;
    }
}

// ---------------------------------------------------------------------------
// Preprocess (x only): gather + RNA-round x into sorted order -> g_Xs.
// W is consumed directly by the GEMM (HMMA truncation on the B operand).
// ---------------------------------------------------------------------------
__global__ void k_prep(const float* __restrict__ x) {
    const int gt = blockIdx.x * blockDim.x + threadIdx.x;
    const int gs = gridDim.x * blockDim.x;

    const uint4* x4 = (const uint4*)x;
    uint4* Xs4 = (uint4*)g_Xs;
    for (int i = gt; i < PADN * DIN / 4; i += gs) {
        const int slot = i >> 9;               // DIN/4 = 512 float4 per row
        const int k4 = i & 511;
        const int tok = g_sorted[slot];
        uint4 v = {0u, 0u, 0u, 0u};
        if (tok >= 0) {
            v = x4[(size_t)tok * 512 + k4];
            v.x = rna(v.x); v.y = rna(v.y); v.z = rna(v.z); v.w = rna(v.w);
        }
        Xs4[i] = v;
    }
}

// ---------------------------------------------------------------------------
// tf32 mma.sync grouped GEMM: 128x256 CTA, 16 warps (32x64 each), BK=32,
// ST=4 cp.async ring (prefetch distance 2), one sync per stage, SW128
// ldmatrix, cvt-free inner loop (A pre-rounded, W truncated by HMMA).
//   y[tok] = relu(x[tok] @ W[e]^T + b[e]).
// ---------------------------------------------------------------------------
__global__ void __launch_bounds__(512, 1)
k_gemm_mma(const float* __restrict__ W, const float* __restrict__ bias,
           float* __restrict__ out) {
    extern __shared__ char smem_raw[];
    const int mt_blk = blockIdx.y;
    const int e = g_tile_expert[mt_blk];
    if (e < 0) return;
    const int n0 = blockIdx.x * BN;
    const int tid = threadIdx.x;
    const int wid = tid >> 5;
    const int lane = tid & 31;

    uint32_t sraw = (uint32_t)__cvta_generic_to_shared(smem_raw);
    uint32_t sbase = (sraw + 1023) & ~1023u;
    char* smem = smem_raw + (sbase - sraw);
    int* s_tok = (int*)(smem + SM_TOK);

    if (tid < BM) s_tok[tid] = g_sorted[mt_blk * BM + tid];
    __syncthreads();

    // ---- Producer geometry (512 threads):
    // A: 4 threads per row, 2x16B chunks each.  B: 2 threads per row, 4x16B.
    const int arow = tid >> 2;
    const int acb = (tid & 3) * 2;
    const float* asrc = g_Xs + (size_t)mt_blk * BM * DIN + (size_t)arow * DIN;
    const int brow = tid >> 1;
    const int bcb = (tid & 1) * 4;
    const float* bsrc = W + (size_t)e * DOUT * DIN + (size_t)(n0 + brow) * DIN;

    uint32_t aoff[2], boff[4];
#pragma unroll
    for (int j = 0; j < 2; j++)
        aoff[j] = SW128((uint32_t)(arow * 128 + (acb + j) * 16));
#pragma unroll
    for (int j = 0; j < 4; j++)
        boff[j] = SW128((uint32_t)(brow * 128 + (bcb + j) * 16));

    auto issue = [&](int it, int bf) {
        const int k0 = it * BK;
        const uint32_t stg = sbase + SM_STG0 + bf * STGB;
#pragma unroll
        for (int j = 0; j < 2; j++)
            cp16(stg + aoff[j], asrc + k0 + (acb + j) * 4);
#pragma unroll
        for (int j = 0; j < 4; j++)
            cp16(stg + BOFF + boff[j], bsrc + k0 + (bcb + j) * 4);
    };

    // ---- ldmatrix lane addressing (32x64 warp tiles, 4x4 warp grid).
    const int g = lane >> 3;
    const int gr = lane & 7;
    const int wm = (wid >> 2) * 32;
    const int wn = (wid & 3) * 64;
    const int a_row_off = wm + ((g & 1) << 3) + gr;
    const int a_kbyte = (g >> 1) << 4;
    const int b_row_off = wn + ((g >> 1) << 3) + gr;
    const int b_kbyte = (g & 1) << 4;

    float acc[2][8][4];
#pragma unroll
    for (int i = 0; i < 2; i++)
#pragma unroll
        for (int j = 0; j < 8; j++)
#pragma unroll
            for (int q = 0; q < 4; q++) acc[i][j][q] = 0.f;

    issue(0, 0); cp_commit();
    issue(1, 1); cp_commit();
    issue(2, 2); cp_commit();

    for (int it = 0; it < NSTG; ++it) {
        const int st = it & (ST - 1);
        cp_wait2();                          // group 'it' complete, 2 in flight
        __syncthreads();
        if (it + 3 < NSTG) issue(it + 3, (it + 3) & (ST - 1));
        cp_commit();                         // empty commits at tail keep count

        const uint32_t aS = sbase + SM_STG0 + st * STGB;
        const uint32_t bS = aS + BOFF;
#pragma unroll
        for (int ks = 0; ks < 4; ks++) {
            uint32_t aF[2][4], bF[8][2];
#pragma unroll
            for (int mt = 0; mt < 2; mt++) {
                uint32_t addr = aS + SW128((uint32_t)((a_row_off + mt * 16) * 128
                                                      + ks * 32 + a_kbyte));
                ldsm4(aF[mt][0], aF[mt][1], aF[mt][2], aF[mt][3], addr);
            }
#pragma unroll
            for (int ntp = 0; ntp < 4; ntp++) {
                uint32_t addr = bS + SW128((uint32_t)((b_row_off + ntp * 16) * 128
                                                      + ks * 32 + b_kbyte));
                ldsm4(bF[2 * ntp][0], bF[2 * ntp][1],
                      bF[2 * ntp + 1][0], bF[2 * ntp + 1][1], addr);
            }
#pragma unroll
            for (int mt = 0; mt < 2; mt++)
#pragma unroll
                for (int nt = 0; nt < 8; nt++)
                    mma_tf32(acc[mt][nt], aF[mt], bF[nt]);
        }
    }

    // ---- Epilogue: bias + ReLU, scatter to token rows.
    const int erow = wm + (lane >> 2);
    const int ecol = n0 + wn + ((lane & 3) << 1);
    float2 bv[8];
#pragma unroll
    for (int nt = 0; nt < 8; nt++)
        bv[nt] = *(const float2*)&bias[(size_t)e * DOUT + ecol + nt * 8];

#pragma unroll
    for (int mt = 0; mt < 2; mt++) {
#pragma unroll
        for (int v = 0; v < 2; v++) {
            const int row = erow + mt * 16 + v * 8;
            const int tok = s_tok[row];
            if (tok < 0) continue;
            float* o = out + (size_t)tok * DOUT + ecol;
#pragma unroll
            for (int nt = 0; nt < 8; nt++) {
                float2 r;
                r.x = fmaxf(acc[mt][nt][2 * v + 0] + bv[nt].x, 0.f);
                r.y = fmaxf(acc[mt][nt][2 * v + 1] + bv[nt].y, 0.f);
                *(float2*)(o + nt * 8) = r;
            }
        }
    }
}

// ---------------------------------------------------------------------------
// Launch: 3 kernels per call (route, prep-x, gemm).
// ---------------------------------------------------------------------------
extern "C" void kernel_launch(void* const* d_in, const int* in_sizes, int n_in,
                              void* d_out, int out_size) {
    const float* x    = (const float*)d_in[0];
    const void*  idxs = d_in[1];
    const float* W    = (const float*)d_in[2];
    const float* b    = (const float*)d_in[3];
    float* out = (float*)d_out;

    k_route<<<1, 1024>>>(idxs);
    k_prep<<<2048, 256>>>(x);

    cudaFuncSetAttribute(k_gemm_mma, cudaFuncAttributeMaxDynamicSharedMemorySize,
                         SMEM_REQ);
    dim3 grid(DOUT / BN, MAXT);            // (8, 136)
    k_gemm_mma<<<grid, 512, SMEM_REQ>>>(W, b, out);
}

// round 14
// speedup vs baseline: 1.0457x; 1.0016x over previous
#include <cuda_runtime.h>
#include <cstdint>

// Problem constants.
#define NTOK 16384
#define DIN  2048
#define DOUT 2048
#define NEXP 8

// GEMM tiling: 128x256 CTA tile, 16 warps (32x64 each, 4x4 grid), persistent.
#define BM 128
#define BN 256
#define BK 32                      // floats per K stage = 128 bytes per row
#define NSTG (DIN / BK)            // 64 stages
#define ST 4                       // cp.async ring depth
#define MAXT (NTOK / BM + NEXP)    // 136 m-tiles worst case
#define PADN (MAXT * BM)           // 17408
#define NXT (DOUT / BN)            // 8 n-tiles
#define NTILE (MAXT * NXT)         // 1088
#define NCTA 152

// SMEM layout (dynamic, offsets from 1024-aligned base).
#define SM_TOK   0                 // 128 ints
#define SM_STG0  1024
#define STGB     49152             // 48 KB per stage: A(16K) + B(32K)
#define BOFF     16384
#define SMEM_REQ (SM_STG0 + ST * STGB + 1024)

#define SW128(o) ((o) ^ (((o) >> 3) & 0x70))

// Scratch (device globals are the sanctioned scratch; no allocations allowed).
__device__ int g_sorted[PADN];
__device__ int g_tile_expert[MAXT];
__device__ int g_tile_ctr;
__device__ __align__(16) float g_Xs[PADN * DIN];          // gathered+rounded x

// ---------------------------------------------------------------------------
// PTX helpers (baseline PTX only — no 'a'-suffix features).
// ---------------------------------------------------------------------------
__device__ __forceinline__ void cp16(uint32_t dst, const void* src) {
    asm volatile("cp.async.cg.shared.global [%0], [%1], 16;"
                 :: "r"(dst), "l"(src));
}
__device__ __forceinline__ void cp_commit() {
    asm volatile("cp.async.commit_group;" ::: "memory");
}
__device__ __forceinline__ void cp_wait2() {
    asm volatile("cp.async.wait_group 2;" ::: "memory");
}
__device__ __forceinline__ void ldsm4(uint32_t& r0, uint32_t& r1, uint32_t& r2,
                                      uint32_t& r3, uint32_t addr) {
    asm volatile("ldmatrix.sync.aligned.m8n8.x4.shared.b16 {%0,%1,%2,%3}, [%4];"
                 : "=r"(r0), "=r"(r1), "=r"(r2), "=r"(r3) : "r"(addr));
}
// Round-to-nearest fp32 -> tf32 bits (applied to x only, in k_prep).
__device__ __forceinline__ uint32_t rna(uint32_t v) {
    uint32_t r;
    asm("cvt.rna.tf32.f32 %0, %1;" : "=r"(r) : "r"(v));
    return r;
}
__device__ __forceinline__ void mma_tf32(float* d, const uint32_t* a,
                                         const uint32_t* b) {
    asm volatile(
        "mma.sync.aligned.m16n8k8.row.col.f32.tf32.tf32.f32 "
        "{%0,%1,%2,%3}, {%4,%5,%6,%7}, {%8,%9}, {%0,%1,%2,%3};"
        : "+f"(d[0]), "+f"(d[1]), "+f"(d[2]), "+f"(d[3])
        : "r"(a[0]), "r"(a[1]), "r"(a[2]), "r"(a[3]), "r"(b[0]), "r"(b[1]));
}

// ---------------------------------------------------------------------------
// Fused routing: ONE CTA. Also resets the persistent tile counter.
// ---------------------------------------------------------------------------
__global__ void k_route(const void* __restrict__ idxs) {
    __shared__ int h[NEXP], fill_s[NEXP];
    __shared__ int s_is64;
    const int tid = threadIdx.x;

    if (tid == 0) {
        g_tile_ctr = 0;
        const int* p = (const int*)idxs;
        int is64 = 1;
        for (int t = 0; t < 32; t++)
            if (p[2 * t + 1] != 0) { is64 = 0; break; }
        s_is64 = is64;
    }
    if (tid < NEXP) h[tid] = 0;
    for (int i = tid; i < PADN; i += 1024) g_sorted[i] = -1;
    __syncthreads();

    const int is64 = s_is64;
    const long long* p64 = (const long long*)idxs;
    const int* p32 = (const int*)idxs;

    for (int i = tid; i < NTOK; i += 1024)
        atomicAdd(&h[is64 ? (int)p64[i] : p32[i]], 1);
    __syncthreads();

    if (tid == 0) {
        int off = 0;
        for (int e = 0; e < NEXP; e++) {
            fill_s[e] = off;
            int nt = (h[e] + BM - 1) / BM;
            for (int t = 0; t < nt; t++) g_tile_expert[off / BM + t] = e;
            off += nt * BM;
        }
        for (int t = off / BM; t < MAXT; t++) g_tile_expert[t] = -1;
    }
    __syncthreads();

    for (int i = tid; i < NTOK; i += 1024) {
        int e = is64 ? (int)p64[i] : p32[i];
        int pos = atomicAdd(&fill_s[e], 1);
        g_sorted[pos] = i;
    }
}

// ---------------------------------------------------------------------------
// Preprocess (x only): gather + RNA-round x into sorted order -> g_Xs.
// W is consumed directly by the GEMM (HMMA truncation on the B operand).
// ---------------------------------------------------------------------------
__global__ void k_prep(const float* __restrict__ x) {
    const int gt = blockIdx.x * blockDim.x + threadIdx.x;
    const int gs = gridDim.x * blockDim.x;

    const uint4* x4 = (const uint4*)x;
    uint4* Xs4 = (uint4*)g_Xs;
    for (int i = gt; i < PADN * DIN / 4; i += gs) {
        const int slot = i >> 9;               // DIN/4 = 512 float4 per row
        const int k4 = i & 511;
        const int tok = g_sorted[slot];
        uint4 v = {0u, 0u, 0u, 0u};
        if (tok >= 0) {
            v = x4[(size_t)tok * 512 + k4];
            v.x = rna(v.x); v.y = rna(v.y); v.z = rna(v.z); v.w = rna(v.w);
        }
        Xs4[i] = v;
    }
}

// ---------------------------------------------------------------------------
// Persistent tf32 mma.sync grouped GEMM: 128x256 tiles pulled from a global
// atomic counter; 16 warps (32x64 each), BK=32, ST=4 cp.async ring, SW128
// ldmatrix, cvt-free inner loop (A pre-rounded, W truncated by HMMA).
//   y[tok] = relu(x[tok] @ W[e]^T + b[e]).
// ---------------------------------------------------------------------------
__global__ void __launch_bounds__(512, 1)
k_gemm_mma(const float* __restrict__ W, const float* __restrict__ bias,
           float* __restrict__ out) {
    extern __shared__ char smem_raw[];
    const int tid = threadIdx.x;
    const int wid = tid >> 5;
    const int lane = tid & 31;

    uint32_t sraw = (uint32_t)__cvta_generic_to_shared(smem_raw);
    uint32_t sbase = (sraw + 1023) & ~1023u;
    char* smem = smem_raw + (sbase - sraw);
    int* s_tok = (int*)(smem + SM_TOK);
    int* s_t = (int*)(smem + SM_TOK + BM * 4);

    // ---- Per-thread constants (independent of tile).
    const int arow = tid >> 2;
    const int acb = (tid & 3) * 2;
    const int brow = tid >> 1;
    const int bcb = (tid & 1) * 4;

    uint32_t aoff[2], boff[4];
#pragma unroll
    for (int j = 0; j < 2; j++)
        aoff[j] = SW128((uint32_t)(arow * 128 + (acb + j) * 16));
#pragma unroll
    for (int j = 0; j < 4; j++)
        boff[j] = SW128((uint32_t)(brow * 128 + (bcb + j) * 16));

    const int g = lane >> 3;
    const int gr = lane & 7;
    const int wm = (wid >> 2) * 32;
    const int wn = (wid & 3) * 64;
    const int a_row_off = wm + ((g & 1) << 3) + gr;
    const int a_kbyte = (g >> 1) << 4;
    const int b_row_off = wn + ((g >> 1) << 3) + gr;
    const int b_kbyte = (g & 1) << 4;

    for (;;) {
        // ---- Pull next tile (work-stealing). Barrier also protects s_tok
        // against overwrite while the previous epilogue still reads it.
        if (tid == 0) *s_t = atomicAdd(&g_tile_ctr, 1);
        __syncthreads();
        const int t = *s_t;
        if (t >= NTILE) break;

        const int mt_blk = t >> 3;             // NXT = 8
        const int e = g_tile_expert[mt_blk];
        const int n0 = (t & 7) * BN;

        if (tid < BM) s_tok[tid] = g_sorted[mt_blk * BM + tid];
        __syncthreads();
        if (e < 0) continue;                   // padding tile

        const float* asrc = g_Xs + (size_t)mt_blk * BM * DIN
                                 + (size_t)arow * DIN;
        const float* bsrc = W + (size_t)e * DOUT * DIN
                              + (size_t)(n0 + brow) * DIN;

        auto issue = [&](int it, int bf) {
            const int k0 = it * BK;
            const uint32_t stg = sbase + SM_STG0 + bf * STGB;
#pragma unroll
            for (int j = 0; j < 2; j++)
                cp16(stg + aoff[j], asrc + k0 + (acb + j) * 4);
#pragma unroll
            for (int j = 0; j < 4; j++)
                cp16(stg + BOFF + boff[j], bsrc + k0 + (bcb + j) * 4);
        };

        float acc[2][8][4];
#pragma unroll
        for (int i = 0; i < 2; i++)
#pragma unroll
            for (int j = 0; j < 8; j++)
#pragma unroll
                for (int q = 0; q < 4; q++) acc[i][j][q] = 0.f;

        issue(0, 0); cp_commit();
        issue(1, 1); cp_commit();
        issue(2, 2); cp_commit();

        for (int it = 0; it < NSTG; ++it) {
            const int st = it & (ST - 1);
            cp_wait2();                      // group 'it' complete, 2 in flight
            __syncthreads();
            if (it + 3 < NSTG) issue(it + 3, (it + 3) & (ST - 1));
            cp_commit();                     // empty commits at tail keep count

            const uint32_t aS = sbase + SM_STG0 + st * STGB;
            const uint32_t bS = aS + BOFF;
#pragma unroll
            for (int ks = 0; ks < 4; ks++) {
                uint32_t aF[2][4], bF[8][2];
#pragma unroll
                for (int mt = 0; mt < 2; mt++) {
                    uint32_t addr = aS + SW128((uint32_t)(
                        (a_row_off + mt * 16) * 128 + ks * 32 + a_kbyte));
                    ldsm4(aF[mt][0], aF[mt][1], aF[mt][2], aF[mt][3], addr);
                }
#pragma unroll
                for (int ntp = 0; ntp < 4; ntp++) {
                    uint32_t addr = bS + SW128((uint32_t)(
                        (b_row_off + ntp * 16) * 128 + ks * 32 + b_kbyte));
                    ldsm4(bF[2 * ntp][0], bF[2 * ntp][1],
                          bF[2 * ntp + 1][0], bF[2 * ntp + 1][1], addr);
                }
#pragma unroll
                for (int mt = 0; mt < 2; mt++)
#pragma unroll
                    for (int nt = 0; nt < 8; nt++)
                        mma_tf32(acc[mt][nt], aF[mt], bF[nt]);
            }
        }

        // ---- Epilogue: bias + ReLU, scatter to token rows.
        const int erow = wm + (lane >> 2);
        const int ecol = n0 + wn + ((lane & 3) << 1);
        float2 bv[8];
#pragma unroll
        for (int nt = 0; nt < 8; nt++)
            bv[nt] = *(const float2*)&bias[(size_t)e * DOUT + ecol + nt * 8];

#pragma unroll
        for (int mt = 0; mt < 2; mt++) {
#pragma unroll
            for (int v = 0; v < 2; v++) {
                const int row = erow + mt * 16 + v * 8;
                const int tok = s_tok[row];
                if (tok < 0) continue;
                float* o = out + (size_t)tok * DOUT + ecol;
#pragma unroll
                for (int nt = 0; nt < 8; nt++) {
                    float2 r;
                    r.x = fmaxf(acc[mt][nt][2 * v + 0] + bv[nt].x, 0.f);
                    r.y = fmaxf(acc[mt][nt][2 * v + 1] + bv[nt].y, 0.f);
                    *(float2*)(o + nt * 8) = r;
                }
            }
        }
    }
}

// ---------------------------------------------------------------------------
// Launch: 3 kernels per call (route, prep-x, persistent gemm).
// ---------------------------------------------------------------------------
extern "C" void kernel_launch(void* const* d_in, const int* in_sizes, int n_in,
                              void* d_out, int out_size) {
    const float* x    = (const float*)d_in[0];
    const void*  idxs = d_in[1];
    const float* W    = (const float*)d_in[2];
    const float* b    = (const float*)d_in[3];
    float* out = (float*)d_out;

    k_route<<<1, 1024>>>(idxs);
    k_prep<<<2048, 256>>>(x);

    cudaFuncSetAttribute(k_gemm_mma, cudaFuncAttributeMaxDynamicSharedMemorySize,
                         SMEM_REQ);
    k_gemm_mma<<<NCTA, 512, SMEM_REQ>>>(W, b, out);
}

// round 16
// speedup vs baseline: 1.8257x; 1.7459x over previous
#include <cuda_runtime.h>
#include <cuda_fp16.h>
#include <cstdint>

// Problem constants.
#define NTOK 16384
#define DIN  2048
#define DOUT 2048
#define NEXP 8

// GEMM tiling: 128x256 CTA tile, 16 warps (32x64 each, 4x4 grid), persistent.
// fp16 operands: K stage = 64 halfs = 128B per row.
#define BM 128
#define BN 256
#define BK 64                      // halfs per K stage = 128 bytes per row
#define NSTG (DIN / BK)            // 32 stages
#define ST 4                       // cp.async ring depth
#define MAXT (NTOK / BM + NEXP)    // 136 m-tiles worst case
#define PADN (MAXT * BM)           // 17408
#define NXT (DOUT / BN)            // 8 n-tiles
#define NTILE (MAXT * NXT)         // 1088
#define NCTA 152

// SMEM layout (dynamic, offsets from 1024-aligned base).
#define SM_TOK   0                 // 128 ints + tile counter
#define SM_STG0  1024
#define STGB     49152             // 48 KB per stage: A(16K) + B(32K)
#define BOFF     16384
#define SMEM_REQ (SM_STG0 + ST * STGB + 1024)

#define SW128(o) ((o) ^ (((o) >> 3) & 0x70))

// Scratch (device globals are the sanctioned scratch; no allocations allowed).
__device__ int g_sorted[PADN];
__device__ int g_tile_expert[MAXT];
__device__ int g_tile_ctr;
__device__ __align__(16) __half g_Wh[NEXP * DOUT * DIN];  // fp16 W
__device__ __align__(16) __half g_Xh[PADN * DIN];         // gathered fp16 x

// ---------------------------------------------------------------------------
// PTX helpers (baseline PTX only — no 'a'-suffix features).
// ---------------------------------------------------------------------------
__device__ __forceinline__ void cp16(uint32_t dst, const void* src) {
    asm volatile("cp.async.cg.shared.global [%0], [%1], 16;"
                 :: "r"(dst), "l"(src));
}
__device__ __forceinline__ void cp_commit() {
    asm volatile("cp.async.commit_group;" ::: "memory");
}
__device__ __forceinline__ void cp_wait2() {
    asm volatile("cp.async.wait_group 2;" ::: "memory");
}
__device__ __forceinline__ void ldsm4(uint32_t& r0, uint32_t& r1, uint32_t& r2,
                                      uint32_t& r3, uint32_t addr) {
    asm volatile("ldmatrix.sync.aligned.m8n8.x4.shared.b16 {%0,%1,%2,%3}, [%4];"
                 : "=r"(r0), "=r"(r1), "=r"(r2), "=r"(r3) : "r"(addr));
}
// Pack two fp32 -> one uint32 of two RN fp16.
__device__ __forceinline__ uint32_t pack_h2(float lo, float hi) {
    uint32_t l = __half_as_ushort(__float2half_rn(lo));
    uint32_t h = __half_as_ushort(__float2half_rn(hi));
    return l | (h << 16);
}
// fp16 MMA: D(f32) += A(f16) * B(f16), 16x8x16.
__device__ __forceinline__ void mma_f16(float* d, const uint32_t* a,
                                        const uint32_t* b) {
    asm volatile(
        "mma.sync.aligned.m16n8k16.row.col.f32.f16.f16.f32 "
        "{%0,%1,%2,%3}, {%4,%5,%6,%7}, {%8,%9}, {%0,%1,%2,%3};"
        : "+f"(d[0]), "+f"(d[1]), "+f"(d[2]), "+f"(d[3])
        : "r"(a[0]), "r"(a[1]), "r"(a[2]), "r"(a[3]), "r"(b[0]), "r"(b[1]));
}

// ---------------------------------------------------------------------------
// Fused routing: ONE CTA. Also resets the persistent tile counter.
// ---------------------------------------------------------------------------
__global__ void k_route(const void* __restrict__ idxs) {
    __shared__ int h[NEXP], fill_s[NEXP];
    __shared__ int s_is64;
    const int tid = threadIdx.x;

    if (tid == 0) {
        g_tile_ctr = 0;
        const int* p = (const int*)idxs;
        int is64 = 1;
        for (int t = 0; t < 32; t++)
            if (p[2 * t + 1] != 0) { is64 = 0; break; }
        s_is64 = is64;
    }
    if (tid < NEXP) h[tid] = 0;
    for (int i = tid; i < PADN; i += 1024) g_sorted[i] = -1;
    __syncthreads();

    const int is64 = s_is64;
    const long long* p64 = (const long long*)idxs;
    const int* p32 = (const int*)idxs;

    for (int i = tid; i < NTOK; i += 1024)
        atomicAdd(&h[is64 ? (int)p64[i] : p32[i]], 1);
    __syncthreads();

    if (tid == 0) {
        int off = 0;
        for (int e = 0; e < NEXP; e++) {
            fill_s[e] = off;
            int nt = (h[e] + BM - 1) / BM;
            for (int t = 0; t < nt; t++) g_tile_expert[off / BM + t] = e;
            off += nt * BM;
        }
        for (int t = off / BM; t < MAXT; t++) g_tile_expert[t] = -1;
    }
    __syncthreads();

    for (int i = tid; i < NTOK; i += 1024) {
        int e = is64 ? (int)p64[i] : p32[i];
        int pos = atomicAdd(&fill_s[e], 1);
        g_sorted[pos] = i;
    }
}

// ---------------------------------------------------------------------------
// Preprocess: W -> fp16 (g_Wh); gather + convert x -> fp16 sorted (g_Xh).
// 8 floats -> one 16B half store per iteration.
// ---------------------------------------------------------------------------
__global__ void k_prep(const float* __restrict__ x, const float* __restrict__ W) {
    const int gt = blockIdx.x * blockDim.x + threadIdx.x;
    const int gs = gridDim.x * blockDim.x;

    const float4* W4 = (const float4*)W;
    uint4* Wh4 = (uint4*)g_Wh;
    for (int i = gt; i < NEXP * DOUT * DIN / 8; i += gs) {
        float4 v0 = W4[2 * i], v1 = W4[2 * i + 1];
        uint4 o;
        o.x = pack_h2(v0.x, v0.y);
        o.y = pack_h2(v0.z, v0.w);
        o.z = pack_h2(v1.x, v1.y);
        o.w = pack_h2(v1.z, v1.w);
        Wh4[i] = o;
    }

    const float4* x4 = (const float4*)x;
    uint4* Xh4 = (uint4*)g_Xh;
    for (int i = gt; i < PADN * DIN / 8; i += gs) {
        const int slot = i >> 8;               // DIN/8 = 256 chunks per row
        const int k8 = i & 255;
        const int tok = g_sorted[slot];
        uint4 o = {0u, 0u, 0u, 0u};
        if (tok >= 0) {
            float4 v0 = x4[(size_t)tok * 512 + 2 * k8];
            float4 v1 = x4[(size_t)tok * 512 + 2 * k8 + 1];
            o.x = pack_h2(v0.x, v0.y);
            o.y = pack_h2(v0.z, v0.w);
            o.z = pack_h2(v1.x, v1.y);
            o.w = pack_h2(v1.z, v1.w);
        }
        Xh4[i] = o;
    }
}

// ---------------------------------------------------------------------------
// Persistent fp16 mma.sync grouped GEMM: 128x256 tiles via atomic counter;
// 16 warps (32x64 each), BK=64 halfs, ST=4 cp.async ring, SW128 ldmatrix,
// m16n8k16 fp16 MMA, fp32 accumulate.
//   y[tok] = relu(x[tok] @ W[e]^T + b[e]).
// ---------------------------------------------------------------------------
__global__ void __launch_bounds__(512, 1)
k_gemm_mma(const float* __restrict__ bias, float* __restrict__ out) {
    extern __shared__ char smem_raw[];
    const int tid = threadIdx.x;
    const int wid = tid >> 5;
    const int lane = tid & 31;

    uint32_t sraw = (uint32_t)__cvta_generic_to_shared(smem_raw);
    uint32_t sbase = (sraw + 1023) & ~1023u;
    char* smem = smem_raw + (sbase - sraw);
    int* s_tok = (int*)(smem + SM_TOK);
    int* s_t = (int*)(smem + SM_TOK + BM * 4);

    // ---- Producer geometry (512 threads, 48 KB/stage):
    // A: 4 threads/row (128 rows x 128B), 2x16B chunks each.
    // B: 2 threads/row (256 rows x 128B), 4x16B chunks each.
    const int arow = tid >> 2;
    const int acb = (tid & 3) * 2;
    const int brow = tid >> 1;
    const int bcb = (tid & 1) * 4;

    uint32_t aoff[2], boff[4];
#pragma unroll
    for (int j = 0; j < 2; j++)
        aoff[j] = SW128((uint32_t)(arow * 128 + (acb + j) * 16));
#pragma unroll
    for (int j = 0; j < 4; j++)
        boff[j] = SW128((uint32_t)(brow * 128 + (bcb + j) * 16));

    // ---- ldmatrix lane addressing (32x64 warp tiles, 4x4 warp grid).
    // Byte layout identical to tf32 version; 16B unit now = 8 halfs (k0-7).
    const int g = lane >> 3;
    const int gr = lane & 7;
    const int wm = (wid >> 2) * 32;
    const int wn = (wid & 3) * 64;
    const int a_row_off = wm + ((g & 1) << 3) + gr;
    const int a_kbyte = (g >> 1) << 4;
    const int b_row_off = wn + ((g >> 1) << 3) + gr;
    const int b_kbyte = (g & 1) << 4;

    for (;;) {
        if (tid == 0) *s_t = atomicAdd(&g_tile_ctr, 1);
        __syncthreads();
        const int t = *s_t;
        if (t >= NTILE) break;

        const int mt_blk = t >> 3;             // NXT = 8
        const int e = g_tile_expert[mt_blk];
        const int n0 = (t & 7) * BN;

        if (tid < BM) s_tok[tid] = g_sorted[mt_blk * BM + tid];
        __syncthreads();
        if (e < 0) continue;                   // padding tile

        const __half* asrc = g_Xh + (size_t)mt_blk * BM * DIN
                                  + (size_t)arow * DIN;
        const __half* bsrc = g_Wh + (size_t)e * DOUT * DIN
                                  + (size_t)(n0 + brow) * DIN;

        auto issue = [&](int it, int bf) {
            const int k0 = it * BK;            // in halfs
            const uint32_t stg = sbase + SM_STG0 + bf * STGB;
#pragma unroll
            for (int j = 0; j < 2; j++)
                cp16(stg + aoff[j], asrc + k0 + (acb + j) * 8);
#pragma unroll
            for (int j = 0; j < 4; j++)
                cp16(stg + BOFF + boff[j], bsrc + k0 + (bcb + j) * 8);
        };

        float acc[2][8][4];
#pragma unroll
        for (int i = 0; i < 2; i++)
#pragma unroll
            for (int j = 0; j < 8; j++)
#pragma unroll
                for (int q = 0; q < 4; q++) acc[i][j][q] = 0.f;

        issue(0, 0); cp_commit();
        issue(1, 1); cp_commit();
        issue(2, 2); cp_commit();

        for (int it = 0; it < NSTG; ++it) {
            const int st = it & (ST - 1);
            cp_wait2();                      // group 'it' complete, 2 in flight
            __syncthreads();
            if (it + 3 < NSTG) issue(it + 3, (it + 3) & (ST - 1));
            cp_commit();                     // empty commits at tail keep count

            const uint32_t aS = sbase + SM_STG0 + st * STGB;
            const uint32_t bS = aS + BOFF;
#pragma unroll
            for (int ks = 0; ks < 4; ks++) {   // each ks = K16 fp16
                uint32_t aF[2][4], bF[8][2];
#pragma unroll
                for (int mt = 0; mt < 2; mt++) {
                    uint32_t addr = aS + SW128((uint32_t)(
                        (a_row_off + mt * 16) * 128 + ks * 32 + a_kbyte));
                    ldsm4(aF[mt][0], aF[mt][1], aF[mt][2], aF[mt][3], addr);
                }
#pragma unroll
                for (int ntp = 0; ntp < 4; ntp++) {
                    uint32_t addr = bS + SW128((uint32_t)(
                        (b_row_off + ntp * 16) * 128 + ks * 32 + b_kbyte));
                    ldsm4(bF[2 * ntp][0], bF[2 * ntp][1],
                          bF[2 * ntp + 1][0], bF[2 * ntp + 1][1], addr);
                }
#pragma unroll
                for (int mt = 0; mt < 2; mt++)
#pragma unroll
                    for (int nt = 0; nt < 8; nt++)
                        mma_f16(acc[mt][nt], aF[mt], bF[nt]);
            }
        }

        // ---- Epilogue: bias + ReLU, scatter to token rows.
        const int erow = wm + (lane >> 2);
        const int ecol = n0 + wn + ((lane & 3) << 1);
        float2 bv[8];
#pragma unroll
        for (int nt = 0; nt < 8; nt++)
            bv[nt] = *(const float2*)&bias[(size_t)e * DOUT + ecol + nt * 8];

#pragma unroll
        for (int mt = 0; mt < 2; mt++) {
#pragma unroll
            for (int v = 0; v < 2; v++) {
                const int row = erow + mt * 16 + v * 8;
                const int tok = s_tok[row];
                if (tok < 0) continue;
                float* o = out + (size_t)tok * DOUT + ecol;
#pragma unroll
                for (int nt = 0; nt < 8; nt++) {
                    float2 r;
                    r.x = fmaxf(acc[mt][nt][2 * v + 0] + bv[nt].x, 0.f);
                    r.y = fmaxf(acc[mt][nt][2 * v + 1] + bv[nt].y, 0.f);
                    *(float2*)(o + nt * 8) = r;
                }
            }
        }
    }
}

// ---------------------------------------------------------------------------
// Launch: 3 kernels per call (route, prep-fp16, persistent gemm).
// ---------------------------------------------------------------------------
extern "C" void kernel_launch(void* const* d_in, const int* in_sizes, int n_in,
                              void* d_out, int out_size) {
    const float* x    = (const float*)d_in[0];
    const void*  idxs = d_in[1];
    const float* W    = (const float*)d_in[2];
    const float* b    = (const float*)d_in[3];
    float* out = (float*)d_out;

    k_route<<<1, 1024>>>(idxs);
    k_prep<<<2048, 256>>>(x, W);

    cudaFuncSetAttribute(k_gemm_mma, cudaFuncAttributeMaxDynamicSharedMemorySize,
                         SMEM_REQ);
    k_gemm_mma<<<NCTA, 512, SMEM_REQ>>>(b, out);
}

// round 17
// speedup vs baseline: 1.8269x; 1.0006x over previous
#include <cuda_runtime.h>
#include <cuda_fp16.h>
#include <cstdint>

// Problem constants.
#define NTOK 16384
#define DIN  2048
#define DOUT 2048
#define NEXP 8

// GEMM tiling: 128x256 CTA tile, 16 warps (32x64 each, 4x4 grid), persistent.
// fp16 operands: K stage = 64 halfs = 128B per row.
#define BM 128
#define BN 256
#define BK 64                      // halfs per K stage = 128 bytes per row
#define NSTG (DIN / BK)            // 32 stages
#define ST 4                       // cp.async ring depth
#define MAXT (NTOK / BM + NEXP)    // 136 m-tiles worst case
#define PADN (MAXT * BM)           // 17408
#define NXT (DOUT / BN)            // 8 n-tiles
#define NTILE (MAXT * NXT)         // 1088
#define NCTA 152

// SMEM layout (dynamic, offsets from 1024-aligned base).
#define SM_TOK   0                 // 128 ints + tile counter
#define SM_STG0  1024
#define STGB     49152             // 48 KB per stage: A(16K) + B(32K)
#define BOFF     16384
#define SMEM_REQ (SM_STG0 + ST * STGB + 1024)

#define SW128(o) ((o) ^ (((o) >> 3) & 0x70))

// Scratch (device globals are the sanctioned scratch; no allocations allowed).
__device__ int g_sorted[PADN];
__device__ int g_tile_expert[MAXT];
__device__ int g_tile_ctr;
__device__ __align__(16) __half g_Wh[NEXP * DOUT * DIN];  // fp16 W
__device__ __align__(16) __half g_Xh[PADN * DIN];         // gathered fp16 x

// ---------------------------------------------------------------------------
// PTX helpers (baseline PTX only — no 'a'-suffix features).
// ---------------------------------------------------------------------------
__device__ __forceinline__ void cp16(uint32_t dst, const void* src) {
    asm volatile("cp.async.cg.shared.global [%0], [%1], 16;"
                 :: "r"(dst), "l"(src));
}
__device__ __forceinline__ void cp_commit() {
    asm volatile("cp.async.commit_group;" ::: "memory");
}
__device__ __forceinline__ void cp_wait2() {
    asm volatile("cp.async.wait_group 2;" ::: "memory");
}
__device__ __forceinline__ void ldsm4(uint32_t& r0, uint32_t& r1, uint32_t& r2,
                                      uint32_t& r3, uint32_t addr) {
    asm volatile("ldmatrix.sync.aligned.m8n8.x4.shared.b16 {%0,%1,%2,%3}, [%4];"
                 : "=r"(r0), "=r"(r1), "=r"(r2), "=r"(r3) : "r"(addr));
}
// Pack two fp32 -> one uint32 of two RN fp16.
__device__ __forceinline__ uint32_t pack_h2(float lo, float hi) {
    uint32_t l = __half_as_ushort(__float2half_rn(lo));
    uint32_t h = __half_as_ushort(__float2half_rn(hi));
    return l | (h << 16);
}
// fp16 MMA: D(f32) += A(f16) * B(f16), 16x8x16.
__device__ __forceinline__ void mma_f16(float* d, const uint32_t* a,
                                        const uint32_t* b) {
    asm volatile(
        "mma.sync.aligned.m16n8k16.row.col.f32.f16.f16.f32 "
        "{%0,%1,%2,%3}, {%4,%5,%6,%7}, {%8,%9}, {%0,%1,%2,%3};"
        : "+f"(d[0]), "+f"(d[1]), "+f"(d[2]), "+f"(d[3])
        : "r"(a[0]), "r"(a[1]), "r"(a[2]), "r"(a[3]), "r"(b[0]), "r"(b[1]));
}

// ---------------------------------------------------------------------------
// Parallel routing: 8 CTAs, one per expert. Every CTA histograms all tokens
// (so it can derive all offsets); CTA e compacts expert e's tokens into its
// region and pads the tail with -1. Order within a bucket is irrelevant to
// the output (y[tok] is position-independent), so output is deterministic.
// ---------------------------------------------------------------------------
__global__ void k_route(const void* __restrict__ idxs) {
    __shared__ int h[NEXP];
    __shared__ int s_is64, s_cnt;
    const int e = blockIdx.x;
    const int tid = threadIdx.x;

    if (tid == 0) {
        s_cnt = 0;
        const int* p = (const int*)idxs;
        int is64 = 1;
        for (int t = 0; t < 32; t++)
            if (p[2 * t + 1] != 0) { is64 = 0; break; }
        s_is64 = is64;
    }
    if (tid < NEXP) h[tid] = 0;
    __syncthreads();

    const int is64 = s_is64;
    const long long* p64 = (const long long*)idxs;
    const int* p32 = (const int*)idxs;

    for (int i = tid; i < NTOK; i += 1024)
        atomicAdd(&h[is64 ? (int)p64[i] : p32[i]], 1);
    __syncthreads();

    // All threads derive this expert's region from the full histogram.
    int off_e = 0;
#pragma unroll
    for (int j = 0; j < NEXP; j++) {
        int ntj = (h[j] + BM - 1) / BM;
        if (j < e) off_e += ntj * BM;
    }
    const int cnt_e = h[e];
    const int nt_e = (cnt_e + BM - 1) / BM;

    // CTA 0: tile->expert map + persistent tile counter.
    if (e == 0 && tid == 0) {
        g_tile_ctr = 0;
        int off = 0;
        for (int j = 0; j < NEXP; j++) {
            int ntj = (h[j] + BM - 1) / BM;
            for (int t = 0; t < ntj; t++) g_tile_expert[off / BM + t] = j;
            off += ntj * BM;
        }
        for (int t = off / BM; t < MAXT; t++) g_tile_expert[t] = -1;
    }

    // Compact this expert's tokens (order irrelevant).
    for (int i = tid; i < NTOK; i += 1024) {
        int id = is64 ? (int)p64[i] : p32[i];
        if (id == e) {
            int pos = atomicAdd(&s_cnt, 1);
            g_sorted[off_e + pos] = i;
        }
    }
    __syncthreads();

    // Pad region tail.
    for (int p = cnt_e + tid; p < nt_e * BM; p += 1024)
        g_sorted[off_e + p] = -1;
}

// ---------------------------------------------------------------------------
// Preprocess: W -> fp16 (g_Wh); gather + convert x -> fp16 sorted (g_Xh).
// 8 floats -> one 16B half store per iteration.
// ---------------------------------------------------------------------------
__global__ void k_prep(const float* __restrict__ x, const float* __restrict__ W) {
    const int gt = blockIdx.x * blockDim.x + threadIdx.x;
    const int gs = gridDim.x * blockDim.x;

    const float4* W4 = (const float4*)W;
    uint4* Wh4 = (uint4*)g_Wh;
    for (int i = gt; i < NEXP * DOUT * DIN / 8; i += gs) {
        float4 v0 = W4[2 * i], v1 = W4[2 * i + 1];
        uint4 o;
        o.x = pack_h2(v0.x, v0.y);
        o.y = pack_h2(v0.z, v0.w);
        o.z = pack_h2(v1.x, v1.y);
        o.w = pack_h2(v1.z, v1.w);
        Wh4[i] = o;
    }

    const float4* x4 = (const float4*)x;
    uint4* Xh4 = (uint4*)g_Xh;
    for (int i = gt; i < PADN * DIN / 8; i += gs) {
        const int slot = i >> 8;               // DIN/8 = 256 chunks per row
        const int k8 = i & 255;
        const int tok = g_sorted[slot];
        uint4 o = {0u, 0u, 0u, 0u};
        if (tok >= 0) {
            float4 v0 = x4[(size_t)tok * 512 + 2 * k8];
            float4 v1 = x4[(size_t)tok * 512 + 2 * k8 + 1];
            o.x = pack_h2(v0.x, v0.y);
            o.y = pack_h2(v0.z, v0.w);
            o.z = pack_h2(v1.x, v1.y);
            o.w = pack_h2(v1.z, v1.w);
        }
        Xh4[i] = o;
    }
}

// ---------------------------------------------------------------------------
// Persistent fp16 mma.sync grouped GEMM: 128x256 tiles via atomic counter;
// 16 warps (32x64 each), BK=64 halfs, ST=4 cp.async ring, SW128 ldmatrix,
// m16n8k16 fp16 MMA, fp32 accumulate.
//   y[tok] = relu(x[tok] @ W[e]^T + b[e]).
// ---------------------------------------------------------------------------
__global__ void __launch_bounds__(512, 1)
k_gemm_mma(const float* __restrict__ bias, float* __restrict__ out) {
    extern __shared__ char smem_raw[];
    const int tid = threadIdx.x;
    const int wid = tid >> 5;
    const int lane = tid & 31;

    uint32_t sraw = (uint32_t)__cvta_generic_to_shared(smem_raw);
    uint32_t sbase = (sraw + 1023) & ~1023u;
    char* smem = smem_raw + (sbase - sraw);
    int* s_tok = (int*)(smem + SM_TOK);
    int* s_t = (int*)(smem + SM_TOK + BM * 4);

    // ---- Producer geometry (512 threads, 48 KB/stage):
    // A: 4 threads/row (128 rows x 128B), 2x16B chunks each.
    // B: 2 threads/row (256 rows x 128B), 4x16B chunks each.
    const int arow = tid >> 2;
    const int acb = (tid & 3) * 2;
    const int brow = tid >> 1;
    const int bcb = (tid & 1) * 4;

    uint32_t aoff[2], boff[4];
#pragma unroll
    for (int j = 0; j < 2; j++)
        aoff[j] = SW128((uint32_t)(arow * 128 + (acb + j) * 16));
#pragma unroll
    for (int j = 0; j < 4; j++)
        boff[j] = SW128((uint32_t)(brow * 128 + (bcb + j) * 16));

    // ---- ldmatrix lane addressing (32x64 warp tiles, 4x4 warp grid).
    const int g = lane >> 3;
    const int gr = lane & 7;
    const int wm = (wid >> 2) * 32;
    const int wn = (wid & 3) * 64;
    const int a_row_off = wm + ((g & 1) << 3) + gr;
    const int a_kbyte = (g >> 1) << 4;
    const int b_row_off = wn + ((g >> 1) << 3) + gr;
    const int b_kbyte = (g & 1) << 4;

    for (;;) {
        if (tid == 0) *s_t = atomicAdd(&g_tile_ctr, 1);
        __syncthreads();
        const int t = *s_t;
        if (t >= NTILE) break;

        const int mt_blk = t >> 3;             // NXT = 8
        const int e = g_tile_expert[mt_blk];
        const int n0 = (t & 7) * BN;

        if (tid < BM) s_tok[tid] = g_sorted[mt_blk * BM + tid];
        __syncthreads();
        if (e < 0) continue;                   // padding tile

        const __half* asrc = g_Xh + (size_t)mt_blk * BM * DIN
                                  + (size_t)arow * DIN;
        const __half* bsrc = g_Wh + (size_t)e * DOUT * DIN
                                  + (size_t)(n0 + brow) * DIN;

        auto issue = [&](int it, int bf) {
            const int k0 = it * BK;            // in halfs
            const uint32_t stg = sbase + SM_STG0 + bf * STGB;
#pragma unroll
            for (int j = 0; j < 2; j++)
                cp16(stg + aoff[j], asrc + k0 + (acb + j) * 8);
#pragma unroll
            for (int j = 0; j < 4; j++)
                cp16(stg + BOFF + boff[j], bsrc + k0 + (bcb + j) * 8);
        };

        float acc[2][8][4];
#pragma unroll
        for (int i = 0; i < 2; i++)
#pragma unroll
            for (int j = 0; j < 8; j++)
#pragma unroll
                for (int q = 0; q < 4; q++) acc[i][j][q] = 0.f;

        issue(0, 0); cp_commit();
        issue(1, 1); cp_commit();
        issue(2, 2); cp_commit();

        for (int it = 0; it < NSTG; ++it) {
            const int st = it & (ST - 1);
            cp_wait2();                      // group 'it' complete, 2 in flight
            __syncthreads();
            if (it + 3 < NSTG) issue(it + 3, (it + 3) & (ST - 1));
            cp_commit();                     // empty commits at tail keep count

            const uint32_t aS = sbase + SM_STG0 + st * STGB;
            const uint32_t bS = aS + BOFF;
#pragma unroll
            for (int ks = 0; ks < 4; ks++) {   // each ks = K16 fp16
                uint32_t aF[2][4], bF[8][2];
#pragma unroll
                for (int mt = 0; mt < 2; mt++) {
                    uint32_t addr = aS + SW128((uint32_t)(
                        (a_row_off + mt * 16) * 128 + ks * 32 + a_kbyte));
                    ldsm4(aF[mt][0], aF[mt][1], aF[mt][2], aF[mt][3], addr);
                }
#pragma unroll
                for (int ntp = 0; ntp < 4; ntp++) {
                    uint32_t addr = bS + SW128((uint32_t)(
                        (b_row_off + ntp * 16) * 128 + ks * 32 + b_kbyte));
                    ldsm4(bF[2 * ntp][0], bF[2 * ntp][1],
                          bF[2 * ntp + 1][0], bF[2 * ntp + 1][1], addr);
                }
#pragma unroll
                for (int mt = 0; mt < 2; mt++)
#pragma unroll
                    for (int nt = 0; nt < 8; nt++)
                        mma_f16(acc[mt][nt], aF[mt], bF[nt]);
            }
        }

        // ---- Epilogue: bias + ReLU, scatter to token rows.
        const int erow = wm + (lane >> 2);
        const int ecol = n0 + wn + ((lane & 3) << 1);
        float2 bv[8];
#pragma unroll
        for (int nt = 0; nt < 8; nt++)
            bv[nt] = *(const float2*)&bias[(size_t)e * DOUT + ecol + nt * 8];

#pragma unroll
        for (int mt = 0; mt < 2; mt++) {
#pragma unroll
            for (int v = 0; v < 2; v++) {
                const int row = erow + mt * 16 + v * 8;
                const int tok = s_tok[row];
                if (tok < 0) continue;
                float* o = out + (size_t)tok * DOUT + ecol;
#pragma unroll
                for (int nt = 0; nt < 8; nt++) {
                    float2 r;
                    r.x = fmaxf(acc[mt][nt][2 * v + 0] + bv[nt].x, 0.f);
                    r.y = fmaxf(acc[mt][nt][2 * v + 1] + bv[nt].y, 0.f);
                    *(float2*)(o + nt * 8) = r;
                }
            }
        }
    }
}

// ---------------------------------------------------------------------------
// Launch: 3 kernels per call (parallel route, prep-fp16, persistent gemm).
// ---------------------------------------------------------------------------
extern "C" void kernel_launch(void* const* d_in, const int* in_sizes, int n_in,
                              void* d_out, int out_size) {
    const float* x    = (const float*)d_in[0];
    const void*  idxs = d_in[1];
    const float* W    = (const float*)d_in[2];
    const float* b    = (const float*)d_in[3];
    float* out = (float*)d_out;

    k_route<<<NEXP, 1024>>>(idxs);
    k_prep<<<2048, 256>>>(x, W);

    cudaFuncSetAttribute(k_gemm_mma, cudaFuncAttributeMaxDynamicSharedMemorySize,
                         SMEM_REQ);
    k_gemm_mma<<<NCTA, 512, SMEM_REQ>>>(b, out);
}